// round 8
// baseline (speedup 1.0000x reference)
#include <cuda_runtime.h>
#include <cstdint>

// Problem constants (match reference_code)
#define USER_NUM  1000000
#define EMBED_DIM 64
#define BATCH     16384

// FM scoring: out[e] = w[u] + w[i] + b + dot(V[u], V[i])
// INPUT is int32 on the wire.
//
// sm_103a only allows L2::evict_last on 256-bit loads (.v8.f32), so use
// 8 lanes per element, 32B per lane per row. This both pins the gathered
// V rows in L2 (steady-state graph replays should become L2-hits) and
// halves the LDG/wavefront count vs the float4 version.
struct f8 { float v[8]; };

__device__ __forceinline__ f8 ldg_el_v8(const float* p) {
    f8 r;
    asm volatile(
        "ld.global.nc.L2::evict_last.v8.f32 {%0,%1,%2,%3,%4,%5,%6,%7}, [%8];"
        : "=f"(r.v[0]), "=f"(r.v[1]), "=f"(r.v[2]), "=f"(r.v[3]),
          "=f"(r.v[4]), "=f"(r.v[5]), "=f"(r.v[6]), "=f"(r.v[7])
        : "l"(p));
    return r;
}

__global__ void __launch_bounds__(256) fm_score_kernel(
    const int*   __restrict__ inp,   // [BATCH, 2] int32
    const float* __restrict__ w,     // [USER_NUM + ITEM_NUM]
    const float* __restrict__ bptr,  // [1]
    const float* __restrict__ V,     // [USER_NUM + ITEM_NUM, 64]
    float*       __restrict__ out)   // [BATCH]
{
    const int gid  = blockIdx.x * blockDim.x + threadIdx.x;
    const int elem = gid >> 3;       // 8 lanes per element
    const int lane = gid & 7;
    if (elem >= BATCH) return;

    const int2 idx = __ldg(reinterpret_cast<const int2*>(inp) + elem);
    const long long u = (long long)idx.x;
    const long long i = (long long)idx.y + USER_NUM;

    const float* up = V + u * EMBED_DIM + lane * 8;   // 32B chunk per lane
    const float* ip = V + i * EMBED_DIM + lane * 8;

    // Two 256-bit gathers back-to-back, pinned to L2 with evict_last.
    const f8 a = ldg_el_v8(up);
    const f8 c = ldg_el_v8(ip);

    // Linear terms issued early (broadcast loads), not after the reduce.
    float wsum = 0.0f;
    if (lane == 0)
        wsum = __ldg(&w[u]) + __ldg(&w[i]) + __ldg(&bptr[0]);

    float dot = 0.0f;
    #pragma unroll
    for (int k = 0; k < 8; k++)
        dot += a.v[k] * c.v[k];

    // Reduce across the 8-lane group (contiguous within the warp).
    #pragma unroll
    for (int off = 4; off > 0; off >>= 1)
        dot += __shfl_xor_sync(0xffffffffu, dot, off);

    if (lane == 0)
        out[elem] = wsum + dot;
}

extern "C" void kernel_launch(void* const* d_in, const int* in_sizes, int n_in,
                              void* d_out, int out_size)
{
    const int*   inp = (const int*)d_in[0];    // INPUT int32 [BATCH,2]
    const float* w   = (const float*)d_in[1];  // w
    const float* b   = (const float*)d_in[2];  // b
    const float* V   = (const float*)d_in[3];  // V
    float*       out = (float*)d_out;          // [BATCH,1] float32

    const int threads = 256;
    const int total   = BATCH * 8;             // 8 lanes per element
    const int blocks  = (total + threads - 1) / threads;
    fm_score_kernel<<<blocks, threads>>>(inp, w, b, V, out);
}

// round 9
// speedup vs baseline: 1.0337x; 1.0337x over previous
#include <cuda_runtime.h>
#include <cstdint>

// Problem constants (match reference_code)
#define USER_NUM  1000000
#define EMBED_DIM 64
#define BATCH     16384

#define THREADS     256
#define E_PER_CTA   64          // elems 0-31: LDG path, 32-63: cp.async path
#define CP_ELEMS    32
#define CP_ROWS     (CP_ELEMS * 2)             // 64 rows x 256B = 16KB
#define CP_CHUNKS   (CP_ROWS * 16)             // 1024 x 16B
#define CP_PER_THR  (CP_CHUNKS / THREADS)      // 4

// FM scoring: out[e] = w[u] + w[i] + b + dot(V[u], V[i]).  INPUT is int32.
//
// Discriminating experiment: LDG misses (L1tex MSHRs) and cp.async.cg
// misses (L1-bypass path) each saturate alone at ~1.36TB/s (R2-R8).
// If their in-flight tracking structures are independent, running both
// streams concurrently in one kernel adds the caps -> ~2x gather rate.
__global__ void __launch_bounds__(THREADS) fm_dual_stream_kernel(
    const int*   __restrict__ inp,   // [BATCH, 2] int32
    const float* __restrict__ w,     // [USER_NUM + ITEM_NUM]
    const float* __restrict__ bptr,  // [1]
    const float* __restrict__ V,     // [USER_NUM + ITEM_NUM, 64]
    float*       __restrict__ out)   // [BATCH]
{
    __shared__ __align__(16) float rows[CP_ROWS][EMBED_DIM];  // 16KB
    __shared__ int sidx[CP_ELEMS * 2];                        // 64 ints

    const int tid    = threadIdx.x;
    const int e0     = blockIdx.x * E_PER_CTA;
    const int grp    = tid >> 4;       // 0..15
    const int lane   = tid & 15;

    // ---- LDG half (elems 0..31): issue gathers immediately, pre-sync ----
    // Group g handles elems 2g and 2g+1 (R3 pattern: one int4 index load).
    const int4 idx = __ldg(reinterpret_cast<const int4*>(inp) + (e0 >> 1) + grp);
    const long long u0 = (long long)idx.x;
    const long long i0 = (long long)idx.y + USER_NUM;
    const long long u1 = (long long)idx.z;
    const long long i1 = (long long)idx.w + USER_NUM;

    const float4 a0 = __ldg(reinterpret_cast<const float4*>(V + u0 * EMBED_DIM) + lane);
    const float4 c0 = __ldg(reinterpret_cast<const float4*>(V + i0 * EMBED_DIM) + lane);
    const float4 a1 = __ldg(reinterpret_cast<const float4*>(V + u1 * EMBED_DIM) + lane);
    const float4 c1 = __ldg(reinterpret_cast<const float4*>(V + i1 * EMBED_DIM) + lane);

    // ---- Stage cp.async-half indices (elems 32..63 -> 64 ints) ----
    if (tid < CP_ELEMS * 2)
        sidx[tid] = __ldg(&inp[(e0 + CP_ELEMS) * 2 + tid]);
    __syncthreads();

    // ---- cp.async half: 4 x 16B per thread, deep pipeline, L1-bypass ----
    #pragma unroll
    for (int k = 0; k < CP_PER_THR; k++) {
        const int c     = tid + k * THREADS;   // 0..1023
        const int r     = c >> 4;              // row 0..63
        const int chunk = c & 15;
        const int e     = r >> 1;
        const int side  = r & 1;
        const unsigned ridx = side ? (unsigned)sidx[2 * e + 1] + USER_NUM
                                   : (unsigned)sidx[2 * e];
        const float* src = V + (size_t)ridx * EMBED_DIM + chunk * 4;
        const uint32_t dst =
            (uint32_t)__cvta_generic_to_shared(&rows[r][chunk * 4]);
        asm volatile("cp.async.cg.shared.global [%0], [%1], 16;"
                     :: "r"(dst), "l"(src) : "memory");
    }
    asm volatile("cp.async.commit_group;" ::: "memory");

    // ---- w sums for all 4 outputs this group owns (early, overlapped) ----
    float ws0 = 0.f, ws1 = 0.f, ws2 = 0.f, ws3 = 0.f;
    if (lane == 0) {
        const float bb = __ldg(&bptr[0]);
        ws0 = __ldg(&w[u0]) + __ldg(&w[i0]) + bb;
        ws1 = __ldg(&w[u1]) + __ldg(&w[i1]) + bb;
        const unsigned u2 = (unsigned)sidx[4 * grp];
        const unsigned i2 = (unsigned)sidx[4 * grp + 1] + USER_NUM;
        const unsigned u3 = (unsigned)sidx[4 * grp + 2];
        const unsigned i3 = (unsigned)sidx[4 * grp + 3] + USER_NUM;
        ws2 = __ldg(&w[u2]) + __ldg(&w[i2]) + bb;
        ws3 = __ldg(&w[u3]) + __ldg(&w[i3]) + bb;
    }

    // ---- LDG-half dots (loads have been in flight the whole time) ----
    float d0 = a0.x * c0.x + a0.y * c0.y + a0.z * c0.z + a0.w * c0.w;
    float d1 = a1.x * c1.x + a1.y * c1.y + a1.z * c1.z + a1.w * c1.w;
    #pragma unroll
    for (int off = 8; off > 0; off >>= 1) {
        d0 += __shfl_xor_sync(0xffffffffu, d0, off);
        d1 += __shfl_xor_sync(0xffffffffu, d1, off);
    }
    if (lane == 0) {
        *reinterpret_cast<float2*>(out + e0 + 2 * grp) = make_float2(ws0 + d0, ws1 + d1);
    }

    // ---- cp.async-half dots from SMEM ----
    asm volatile("cp.async.wait_group 0;" ::: "memory");
    __syncthreads();

    // Group g handles cp elems 2g, 2g+1 -> rows 4g..4g+3.
    const float4 a2 = *reinterpret_cast<const float4*>(&rows[4 * grp][lane * 4]);
    const float4 c2 = *reinterpret_cast<const float4*>(&rows[4 * grp + 1][lane * 4]);
    const float4 a3 = *reinterpret_cast<const float4*>(&rows[4 * grp + 2][lane * 4]);
    const float4 c3 = *reinterpret_cast<const float4*>(&rows[4 * grp + 3][lane * 4]);

    float d2 = a2.x * c2.x + a2.y * c2.y + a2.z * c2.z + a2.w * c2.w;
    float d3 = a3.x * c3.x + a3.y * c3.y + a3.z * c3.z + a3.w * c3.w;
    #pragma unroll
    for (int off = 8; off > 0; off >>= 1) {
        d2 += __shfl_xor_sync(0xffffffffu, d2, off);
        d3 += __shfl_xor_sync(0xffffffffu, d3, off);
    }
    if (lane == 0) {
        *reinterpret_cast<float2*>(out + e0 + CP_ELEMS + 2 * grp) =
            make_float2(ws2 + d2, ws3 + d3);
    }
}

extern "C" void kernel_launch(void* const* d_in, const int* in_sizes, int n_in,
                              void* d_out, int out_size)
{
    const int*   inp = (const int*)d_in[0];    // INPUT int32 [BATCH,2]
    const float* w   = (const float*)d_in[1];  // w
    const float* b   = (const float*)d_in[2];  // b
    const float* V   = (const float*)d_in[3];  // V
    float*       out = (float*)d_out;          // [BATCH,1] float32

    const int blocks = BATCH / E_PER_CTA;      // 256
    fm_dual_stream_kernel<<<blocks, THREADS>>>(inp, w, b, V, out);
}